// round 12
// baseline (speedup 1.0000x reference)
#include <cuda_runtime.h>
#include <cuda_bf16.h>
#include <cuda_fp16.h>
#include <cstdint>
#include <cstddef>

#define N_NODES 1024
#define F_IN    32
#define HID     64
#define OUT     32
#define I_TILE  8
#define J_TILE  16
#define JITERS  16    // j-tiles per block (single-wave grid: 512 CTAs)
#define THREADS 256

#if defined(__CUDA_ARCH__) && (defined(__CUDA_ARCH_FEAT_SM103_ALL) || \
                               defined(__CUDA_ARCH_FEAT_SM100_ALL) || \
                               defined(__CUDA_ARCH_FAMILY_SPECIFIC__))
#define USE_TC 1
#else
#define USE_TC 0
#endif

__device__ float g_A[N_NODES * HID];   // A[i,h] = Emb[i,:] . W1[h, :F]
__device__ float g_B[N_NODES * HID];   // B[j,h] = Emb[j,:] . W1[h, F:]

// ---------------------------------------------------------------------------
// Kernel 1: A/B precompute — smem-staged W1 (padded, conflict-free), emb
// broadcast, coalesced stores. 256 blocks x 256 thr; block = 4 i-rows.
// ---------------------------------------------------------------------------
__global__ __launch_bounds__(256)
void precompute_AB(const float* __restrict__ Emb,
                   const float* __restrict__ W1) {
    __shared__ float w1s[HID][2 * F_IN + 1];   // [64][65] pad -> bank=(h+f)&31
    __shared__ float embs[4][F_IN + 1];
    const int tid = threadIdx.x;
    const int ibase = blockIdx.x * 4;

    for (int p = tid; p < HID * 2 * F_IN; p += 256) {
        int r = p >> 6, c = p & 63;
        w1s[r][c] = W1[p];
    }
    if (tid < 4 * F_IN)
        embs[tid >> 5][tid & 31] = Emb[ibase * F_IN + tid];
    __syncthreads();

    const int il = tid >> 6;      // 0..3 (broadcast within warp)
    const int h  = tid & 63;
    float sa = 0.f, sb = 0.f;
#pragma unroll
    for (int f = 0; f < F_IN; ++f) {
        float e = embs[il][f];
        sa = fmaf(e, w1s[h][f], sa);
        sb = fmaf(e, w1s[h][F_IN + f], sb);
    }
    const int idx = (ibase + il) * HID + h;   // consecutive tid -> coalesced
    g_A[idx] = sa;
    g_B[idx] = sb;
}

// ---------------------------------------------------------------------------
// Helpers
// ---------------------------------------------------------------------------
__device__ __forceinline__ unsigned smem_u32(const void* p) {
    unsigned a;
    asm("{ .reg .u64 t; cvta.to.shared.u64 t, %1; cvt.u32.u64 %0, t; }"
        : "=r"(a) : "l"(p));
    return a;
}

__device__ __forceinline__ unsigned long long pack2(float lo, float hi) {
    unsigned long long r;
    asm("mov.b64 %0, {%1, %2};"
        : "=l"(r) : "r"(__float_as_uint(lo)), "r"(__float_as_uint(hi)));
    return r;
}

__device__ __forceinline__ void unpack2(unsigned long long v, float& lo, float& hi) {
    unsigned a, b;
    asm("mov.b64 {%0, %1}, %2;" : "=r"(a), "=r"(b) : "l"(v));
    lo = __uint_as_float(a);
    hi = __uint_as_float(b);
}

__device__ __forceinline__ unsigned long long lds_u64(unsigned addr) {
    unsigned long long r;
    asm volatile("ld.shared.b64 %0, [%1];" : "=l"(r) : "r"(addr));
    return r;
}

#define FFMA2(acc, a, b) \
    asm("fma.rn.f32x2 %0, %1, %2, %0;" : "+l"(acc) : "l"(a), "l"(b))

__device__ __forceinline__ float tanh_f(float x) {
    float t;
    asm("tanh.approx.f32 %0, %1;" : "=f"(t) : "f"(x));
    return t;
}

// swish(x) for the fallback path (full form)
__device__ __forceinline__ float swish_fast(float x) {
    float h = 0.5f * x;
    float t = tanh_f(h);
    return fmaf(h, t, h);
}

// Given h = x/2 already: swish(x) = h*(1+tanh(h))
__device__ __forceinline__ float swish_from_half(float h) {
    float t = tanh_f(h);
    return fmaf(h, t, h);
}

// pack two f32 -> f16x2 (first arg -> low half)
__device__ __forceinline__ unsigned cvt2f16(float lo, float hi) {
    unsigned r;
    asm("cvt.rn.f16x2.f32 %0, %1, %2;" : "=r"(r) : "f"(hi), "f"(lo));
    return r;
}

#if USE_TC
__device__ __forceinline__ bool elect_one() {
    unsigned pred;
    asm volatile("{\n\t.reg .pred p;\n\telect.sync _|p, 0xFFFFFFFF;\n\t"
                 "selp.b32 %0, 1, 0, p;\n\t}" : "=r"(pred));
    return pred != 0;
}

__device__ __forceinline__ void mbar_init(unsigned addr, unsigned cnt) {
    asm volatile("mbarrier.init.shared.b64 [%0], %1;" :: "r"(addr), "r"(cnt) : "memory");
}

__device__ __forceinline__ void mbar_inval(unsigned addr) {
    asm volatile("mbarrier.inval.shared.b64 [%0];" :: "r"(addr) : "memory");
}

__device__ __forceinline__ void mbar_arrive(unsigned addr) {
    asm volatile("mbarrier.arrive.release.cta.shared::cta.b64 _, [%0];"
                 :: "r"(addr) : "memory");
}

__device__ __forceinline__ void mbar_wait(unsigned addr, unsigned parity) {
    asm volatile(
        "{\n\t.reg .pred P;\n\t"
        "WL_%=:\n\t"
        "mbarrier.try_wait.parity.acquire.cta.shared::cta.b64 P, [%0], %1, 0x989680;\n\t"
        "@P bra.uni WD_%=;\n\t"
        "bra.uni WL_%=;\n\t"
        "WD_%=:\n\t}"
        :: "r"(addr), "r"(parity) : "memory");
}

// SW128 K-major smem descriptor: layout=2, version=1, SBO=64, LBO=1
__device__ __forceinline__ unsigned long long sdesc(unsigned addr) {
    const unsigned long long base =
        (2ull << 61) | (1ull << 46) | (64ull << 32) | (1ull << 16);
    return base | ((unsigned long long)(addr >> 4) & 0x3FFF);
}

// idesc kind::f16: dtype=F32, atype=btype=F16(0), N=32, M=128 -> 0x8080010
#define MMA_IDESC ((1u << 4) | ((OUT / 8) << 17) | (8u << 24))

// TS-form: A operand in TMEM
__device__ __forceinline__ void mma_f16_ts(unsigned d_tmem, unsigned a_tmem,
                                           unsigned long long b_desc,
                                           unsigned en) {
    asm volatile(
        "{\n\t.reg .pred p;\n\t"
        "setp.ne.u32 p, %5, 0;\n\t"
        "tcgen05.mma.cta_group::1.kind::f16 [%0], [%1], %2, %3, {%4, %4, %4, %4}, p;\n\t"
        "}"
        :: "r"(d_tmem), "r"(a_tmem), "l"(b_desc), "r"(MMA_IDESC), "r"(0u), "r"(en)
        : "memory");
}

#define STTM_X16(addr, r) \
    asm volatile( \
        "tcgen05.st.sync.aligned.32x32b.x16.b32 [%0], " \
        "{%1, %2, %3, %4, %5, %6, %7, %8, " \
        " %9, %10, %11, %12, %13, %14, %15, %16};" \
        :: "r"(addr), \
           "r"((r)[0]),  "r"((r)[1]),  "r"((r)[2]),  "r"((r)[3]), \
           "r"((r)[4]),  "r"((r)[5]),  "r"((r)[6]),  "r"((r)[7]), \
           "r"((r)[8]),  "r"((r)[9]),  "r"((r)[10]), "r"((r)[11]), \
           "r"((r)[12]), "r"((r)[13]), "r"((r)[14]), "r"((r)[15]) \
        : "memory")

#define LDTM_X16(r, addr) \
    asm volatile( \
        "tcgen05.ld.sync.aligned.32x32b.x16.b32 " \
        "{%0, %1, %2, %3, %4, %5, %6, %7, " \
        " %8, %9, %10, %11, %12, %13, %14, %15}, [%16];" \
        : "=r"((r)[0]),  "=r"((r)[1]),  "=r"((r)[2]),  "=r"((r)[3]), \
          "=r"((r)[4]),  "=r"((r)[5]),  "=r"((r)[6]),  "=r"((r)[7]), \
          "=r"((r)[8]),  "=r"((r)[9]),  "=r"((r)[10]), "=r"((r)[11]), \
          "=r"((r)[12]), "=r"((r)[13]), "=r"((r)[14]), "=r"((r)[15]) \
        : "r"(addr))
#endif  // USE_TC

// ---------------------------------------------------------------------------
// Dynamic SMEM layout. Total 22912 B.
// ---------------------------------------------------------------------------
#define SM_TMEM   0
#define SM_FULL0  8
#define SM_FULL1  16
#define SM_EMPTY0 24
#define SM_EMPTY1 32
#define SM_BSF0   40
#define SM_BSF1   48
#define SM_BSE0   56
#define SM_BSE1   64
#define SM_WHI    1024                    // 32 x 64 f16 SW128 = 4KB
#define SM_WLO    (SM_WHI + 4096)         // 5120
#define SM_BS0    (SM_WLO + 4096)         // 9216  (16 rows x 64 f, XOR layout)
#define SM_BS1    (SM_BS0 + 4096)         // 13312
#define SM_AS     (SM_BS1 + 4096)         // 17408 (8 rows x 64 f = 2KB)
#define SM_B1     (SM_AS + 2048)          // 19456 (0.5*b1)
#define SM_B2     (SM_B1 + 256)           // 19712 (0.5*b2)
#define SM_CJ     (SM_B2 + 128)           // 19840 (256 j x 3 f = 3072B)
#define SM_TOTAL  (SM_CJ + 3072)          // 22912

// Fallback layout (front of same buffer)
#define FB_W2P  0
#define FB_B1   (FB_W2P + HID * 16 * 8)
#define FB_B2   (FB_B1 + HID * 4)

#define SWZ(off) ((off) ^ (((off) >> 3) & 0x70))
// Bs addressing: buffer buf, row jl (256B), float4 slot c4 at (c4 ^ jl)*16
#define BS_ADDR(buf, jl, c4) \
    (SM_BS0 + ((unsigned)(buf) << 12) + ((jl) << 8) + ((unsigned)((c4) ^ (jl)) << 4))

// TMEM column offsets (alloc 128 cols)
#define TM_D0 0
#define TM_D1 32
#define TM_A0 64
#define TM_A1 96

// ---------------------------------------------------------------------------
// Kernel 2: warp-specialized fused edge MLP, 4 CTAs/SM (regs forced <=64).
// warps 0-3 producers: h1 (two x16 halves), STTM, MMA, commit.
// warps 4-7 consumers: LDTM (two x16 halves), swish, store, B staging ahead.
// ---------------------------------------------------------------------------
__global__ __launch_bounds__(THREADS, 4)
void edge_mlp_tc(const float* __restrict__ Edges,
                 const float* __restrict__ Coords,
                 const float* __restrict__ b1,
                 const float* __restrict__ W2,
                 const float* __restrict__ b2,
                 float* __restrict__ out) {
    extern __shared__ char smem[];
    const int tid  = threadIdx.x;
    const int warp = tid >> 5;
    const int ibase = blockIdx.y * I_TILE;
    const int jblk  = blockIdx.x * (J_TILE * JITERS);

#if USE_TC
    const unsigned sb = smem_u32(smem);
    if (warp == 0) {
        asm volatile("tcgen05.alloc.cta_group::1.sync.aligned.shared::cta.b32 [%0], %1;"
                     :: "r"(sb + SM_TMEM), "r"(128u) : "memory");
        asm volatile("tcgen05.relinquish_alloc_permit.cta_group::1.sync.aligned;");
    }
    if (tid == 0) {
        mbar_init(sb + SM_FULL0, 1);
        mbar_init(sb + SM_FULL1, 1);
        mbar_init(sb + SM_EMPTY0, 4);   // 4 consumer warps
        mbar_init(sb + SM_EMPTY1, 4);
        mbar_init(sb + SM_BSF0, 4);     // 4 consumer warps (stagers)
        mbar_init(sb + SM_BSF1, 4);
        mbar_init(sb + SM_BSE0, 4);     // 4 producer warps
        mbar_init(sb + SM_BSE1, 4);
    }

    // ---- one-time staging: W2 (fp16 hi/lo, SW128), A rows, 0.5*b1/b2, Cj ----
    for (int p = tid; p < OUT * 32; p += THREADS) {
        int o = p >> 5, h2 = p & 31;
        float w0 = W2[o * HID + 2 * h2];
        float w1 = W2[o * HID + 2 * h2 + 1];
        unsigned hi = cvt2f16(w0, w1);
        float r0 = w0 - __half2float(__ushort_as_half((unsigned short)(hi & 0xFFFF)));
        float r1 = w1 - __half2float(__ushort_as_half((unsigned short)(hi >> 16)));
        unsigned lo = cvt2f16(r0, r1);
        unsigned sw = SWZ((unsigned)(o * 128 + h2 * 4));
        *(unsigned*)(smem + SM_WHI + sw) = hi;
        *(unsigned*)(smem + SM_WLO + sw) = lo;
    }
    if (tid < 128)
        ((float4*)(smem + SM_AS))[tid] = ((const float4*)(g_A + ibase * HID))[tid];
    if (tid < HID) ((float*)(smem + SM_B1))[tid] = 0.5f * b1[tid];
    else if (tid < HID + OUT) ((float*)(smem + SM_B2))[tid - HID] = 0.5f * b2[tid - HID];
    for (int p = tid; p < 3 * J_TILE * JITERS; p += THREADS)
        ((float*)(smem + SM_CJ))[p] = Coords[jblk * 3 + p];

    asm volatile("fence.proxy.async.shared::cta;" ::: "memory");
    __syncthreads();

    unsigned tmem;
    asm("ld.shared.b32 %0, [%1];" : "=r"(tmem) : "r"(sb + SM_TMEM));

    if (tid < 128) {
        // =========================== PRODUCERS ===========================
        const int irow = tid >> 4;
        const int i    = ibase + irow;
        const int jl   = tid & 15;
        const unsigned warp_off = (unsigned)warp << 21;

        const float cx = Coords[i * 3 + 0];
        const float cy = Coords[i * 3 + 1];
        const float cz = Coords[i * 3 + 2];

        const float4* Asr = (const float4*)(smem + SM_AS + irow * 256);
        const float4* b1s = (const float4*)(smem + SM_B1);   // pre-halved
        const float*  CjS = (const float*)(smem + SM_CJ);
        const unsigned long long whiD = sdesc(sb + SM_WHI);
        const unsigned long long wloD = sdesc(sb + SM_WLO);

        const float* erow = Edges + (size_t)i * N_NODES + jblk + jl;
        float epre = __ldg(erow);                   // Edges for t=0

        for (int t = 0; t < JITERS; ++t) {
            const int slot = t & 1;

            float ecur = epre;
            if (t < JITERS - 1) epre = __ldg(erow + (t + 1) * J_TILE);

            const int cjx = (t * J_TILE + jl) * 3;
            float dx = cx - CjS[cjx + 0];
            float dy = cy - CjS[cjx + 1];
            float dz = cz - CjS[cjx + 2];
            float d2 = dx * dx + dy * dy + dz * dz;
            float dist = (d2 > 0.f) ? d2 * rsqrtf(d2) : 0.f;
            const float wh = 0.5f * ecur * dist;    // 0.5 folded in

            // wait for consumer-staged Bs[slot] (normally already complete)
            mbar_wait(sb + SM_BSF0 + slot * 8, (t >> 1) & 1);

            const unsigned atm = tmem + (slot ? TM_A1 : TM_A0);

            // ---- half 1: hidden units 0..31 -> 16 f16x2 regs ----
            unsigned v[16];
#pragma unroll
            for (int c = 0; c < 4; ++c) {
                float4 a0 = Asr[2 * c];
                float4 a1 = Asr[2 * c + 1];
                float4 p0 = *(const float4*)(smem + BS_ADDR(slot, jl, 2 * c));
                float4 p1 = *(const float4*)(smem + BS_ADDR(slot, jl, 2 * c + 1));
                float4 q0 = b1s[2 * c];
                float4 q1 = b1s[2 * c + 1];
                float g0 = swish_from_half(fmaf(wh, a0.x + p0.x, q0.x));
                float g1 = swish_from_half(fmaf(wh, a0.y + p0.y, q0.y));
                float g2 = swish_from_half(fmaf(wh, a0.z + p0.z, q0.z));
                float g3 = swish_from_half(fmaf(wh, a0.w + p0.w, q0.w));
                float g4 = swish_from_half(fmaf(wh, a1.x + p1.x, q1.x));
                float g5 = swish_from_half(fmaf(wh, a1.y + p1.y, q1.y));
                float g6 = swish_from_half(fmaf(wh, a1.z + p1.z, q1.z));
                float g7 = swish_from_half(fmaf(wh, a1.w + p1.w, q1.w));
                v[4 * c + 0] = cvt2f16(g0, g1);
                v[4 * c + 1] = cvt2f16(g2, g3);
                v[4 * c + 2] = cvt2f16(g4, g5);
                v[4 * c + 3] = cvt2f16(g6, g7);
            }

            // A[slot] reuse safe only after MMA[t-2] completed
            if (t >= 2) mbar_wait(sb + SM_FULL0 + slot * 8, ((t - 2) >> 1) & 1);
            STTM_X16(atm + warp_off, v);

            // ---- half 2: hidden units 32..63 ----
#pragma unroll
            for (int c = 4; c < 8; ++c) {
                float4 a0 = Asr[2 * c];
                float4 a1 = Asr[2 * c + 1];
                float4 p0 = *(const float4*)(smem + BS_ADDR(slot, jl, 2 * c));
                float4 p1 = *(const float4*)(smem + BS_ADDR(slot, jl, 2 * c + 1));
                float4 q0 = b1s[2 * c];
                float4 q1 = b1s[2 * c + 1];
                float g0 = swish_from_half(fmaf(wh, a0.x + p0.x, q0.x));
                float g1 = swish_from_half(fmaf(wh, a0.y + p0.y, q0.y));
                float g2 = swish_from_half(fmaf(wh, a0.z + p0.z, q0.z));
                float g3 = swish_from_half(fmaf(wh, a0.w + p0.w, q0.w));
                float g4 = swish_from_half(fmaf(wh, a1.x + p1.x, q1.x));
                float g5 = swish_from_half(fmaf(wh, a1.y + p1.y, q1.y));
                float g6 = swish_from_half(fmaf(wh, a1.z + p1.z, q1.z));
                float g7 = swish_from_half(fmaf(wh, a1.w + p1.w, q1.w));
                v[4 * (c - 4) + 0] = cvt2f16(g0, g1);
                v[4 * (c - 4) + 1] = cvt2f16(g2, g3);
                v[4 * (c - 4) + 2] = cvt2f16(g4, g5);
                v[4 * (c - 4) + 3] = cvt2f16(g6, g7);
            }

            // Bs[slot] fully consumed -> release for restaging (tile t+2)
            __syncwarp();
            if ((tid & 31) == 0) mbar_arrive(sb + SM_BSE0 + slot * 8);

            STTM_X16(atm + 16 + warp_off, v);
            asm volatile("tcgen05.wait::st.sync.aligned;" ::: "memory");
            asm volatile("tcgen05.fence::before_thread_sync;" ::: "memory");

            asm volatile("bar.sync 1, 128;" ::: "memory");   // all STTM done

            if (warp == 0 && elect_one()) {
                asm volatile("tcgen05.fence::after_thread_sync;" ::: "memory");
                if (t >= 2) mbar_wait(sb + SM_EMPTY0 + slot * 8, ((t - 2) >> 1) & 1);
                const unsigned dtm = tmem + (slot ? TM_D1 : TM_D0);
                unsigned en = 0;
#pragma unroll
                for (int k = 0; k < 4; ++k) { mma_f16_ts(dtm, atm + k * 8, whiD + 2 * k, en); en = 1; }
#pragma unroll
                for (int k = 0; k < 4; ++k) { mma_f16_ts(dtm, atm + k * 8, wloD + 2 * k, 1); }
                asm volatile(
                    "tcgen05.commit.cta_group::1.mbarrier::arrive::one.shared::cluster.b64 [%0];"
                    :: "r"(sb + SM_FULL0 + (unsigned)slot * 8) : "memory");
            }
        }
    } else {
        // =========================== CONSUMERS ===========================
        const int ctid = tid - 128;
        const int i    = ibase + (ctid >> 4);
        const int jfix = ctid & 15;
        const float4* b2s = (const float4*)(smem + SM_B2);   // pre-halved

        // prologue: stage B tiles 0 and 1
#pragma unroll
        for (int u = 0; u < 2; ++u) {
            const float4* src = (const float4*)(g_B + (jblk + u * J_TILE) * HID);
#pragma unroll
            for (int p = ctid; p < 256; p += 128) {
                int jj = p >> 4, c4 = p & 15;
                *(float4*)(smem + BS_ADDR(u, jj, c4)) = src[p];
            }
            __syncwarp();
            if ((tid & 31) == 0) mbar_arrive(sb + SM_BSF0 + u * 8);
        }

        for (int t = 0; t < JITERS; ++t) {
            const int slot = t & 1;
            mbar_wait(sb + SM_FULL0 + slot * 8, (t >> 1) & 1);
            asm volatile("tcgen05.fence::after_thread_sync;" ::: "memory");

            const unsigned dtm = tmem + (slot ? TM_D1 : TM_D0);
            const size_t orow =
                ((size_t)i * N_NODES + (jblk + t * J_TILE + jfix)) * OUT;

            unsigned d[16];
            // ---- half 1: outputs 0..15 ----
            LDTM_X16(d, dtm);
            asm volatile("tcgen05.wait::ld.sync.aligned;" ::: "memory");
#pragma unroll
            for (int q = 0; q < 4; ++q) {
                float4 bq = b2s[q];                       // 0.5*b2
                float h0 = fmaf(__uint_as_float(d[4 * q + 0]), 0.5f, bq.x);
                float h1 = fmaf(__uint_as_float(d[4 * q + 1]), 0.5f, bq.y);
                float h2 = fmaf(__uint_as_float(d[4 * q + 2]), 0.5f, bq.z);
                float h3 = fmaf(__uint_as_float(d[4 * q + 3]), 0.5f, bq.w);
                float4 o4;
                o4.x = swish_from_half(h0);
                o4.y = swish_from_half(h1);
                o4.z = swish_from_half(h2);
                o4.w = swish_from_half(h3);
                *(float4*)(out + orow + 4 * q) = o4;
            }
            // ---- half 2: outputs 16..31 ----
            LDTM_X16(d, dtm + 16);
            asm volatile("tcgen05.wait::ld.sync.aligned;" ::: "memory");
            asm volatile("tcgen05.fence::before_thread_sync;" ::: "memory");
            if ((tid & 31) == 0) mbar_arrive(sb + SM_EMPTY0 + slot * 8);
#pragma unroll
            for (int q = 0; q < 4; ++q) {
                float4 bq = b2s[q + 4];
                float h0 = fmaf(__uint_as_float(d[4 * q + 0]), 0.5f, bq.x);
                float h1 = fmaf(__uint_as_float(d[4 * q + 1]), 0.5f, bq.y);
                float h2 = fmaf(__uint_as_float(d[4 * q + 2]), 0.5f, bq.z);
                float h3 = fmaf(__uint_as_float(d[4 * q + 3]), 0.5f, bq.w);
                float4 o4;
                o4.x = swish_from_half(h0);
                o4.y = swish_from_half(h1);
                o4.z = swish_from_half(h2);
                o4.w = swish_from_half(h3);
                *(float4*)(out + orow + 16 + 4 * q) = o4;
            }

            // restage Bs[slot] with tile t+2 (producer is ~1 iter behind need)
            if (t < JITERS - 2) {
                mbar_wait(sb + SM_BSE0 + slot * 8, (t >> 1) & 1);
                const float4* src =
                    (const float4*)(g_B + (jblk + (t + 2) * J_TILE) * HID);
#pragma unroll
                for (int p = ctid; p < 256; p += 128) {
                    int jj = p >> 4, c4 = p & 15;
                    *(float4*)(smem + BS_ADDR(slot, jj, c4)) = src[p];
                }
                __syncwarp();
                if ((tid & 31) == 0) mbar_arrive(sb + SM_BSF0 + slot * 8);
            }
        }
    }

    __syncthreads();
    if (tid == 0) {
        mbar_inval(sb + SM_FULL0);
        mbar_inval(sb + SM_FULL1);
        mbar_inval(sb + SM_EMPTY0);
        mbar_inval(sb + SM_EMPTY1);
        mbar_inval(sb + SM_BSF0);
        mbar_inval(sb + SM_BSF1);
        mbar_inval(sb + SM_BSE0);
        mbar_inval(sb + SM_BSE1);
    }
    __syncthreads();
    if (warp == 0) {
        asm volatile("tcgen05.dealloc.cta_group::1.sync.aligned.b32 %0, %1;"
                     :: "r"(tmem), "r"(128u));
    }
#else
    // ===================== scalar FFMA2 fallback (compile-only) =====================
    float2* W2p = (float2*)(smem + FB_W2P);
    float*  b1f = (float*)(smem + FB_B1);
    float*  b2f = (float*)(smem + FB_B2);
    for (int p = tid; p < HID * 16; p += THREADS) {
        int h = p >> 4, o2 = p & 15;
        W2p[h * 16 + o2] = make_float2(W2[(2 * o2) * HID + h],
                                       W2[(2 * o2 + 1) * HID + h]);
    }
    if (tid < HID) b1f[tid] = b1[tid];
    if (tid < OUT) b2f[tid] = b2[tid];
    __syncthreads();

    if (tid < 128) {
        const int i  = ibase + (tid >> 4);
        const int jl = tid & 15;
        const float cx = Coords[i * 3 + 0];
        const float cy = Coords[i * 3 + 1];
        const float cz = Coords[i * 3 + 2];
        const float4* Ar = (const float4*)(g_A + i * HID);
        const unsigned w2sm = smem_u32(W2p);

        for (int it = 0; it < JITERS; ++it) {
            const int j = jblk + it * J_TILE + jl;
            float dx = cx - Coords[j * 3 + 0];
            float dy = cy - Coords[j * 3 + 1];
            float dz = cz - Coords[j * 3 + 2];
            float d2 = dx * dx + dy * dy + dz * dz;
            float dist = (d2 > 0.f) ? d2 * rsqrtf(d2) : 0.f;
            const float w = Edges[(size_t)i * N_NODES + j] * dist;

            const float4* Br = (const float4*)(g_B + j * HID);
            unsigned long long acc[16];
#pragma unroll
            for (int o2 = 0; o2 < 16; ++o2) acc[o2] = 0ull;

#pragma unroll 4
            for (int c = 0; c < 16; ++c) {
                float4 a  = __ldg(Ar + c);
                float4 bb = __ldg(Br + c);
                float4 bv = __ldg(((const float4*)b1) + c);
                float av[4] = {a.x, a.y, a.z, a.w};
                float pv[4] = {bb.x, bb.y, bb.z, bb.w};
                float cv[4] = {bv.x, bv.y, bv.z, bv.w};
#pragma unroll
                for (int k = 0; k < 4; ++k) {
                    float g = swish_fast(fmaf(w, av[k] + pv[k], cv[k]));
                    unsigned long long g2 = pack2(g, g);
                    unsigned base = w2sm + (unsigned)(4 * c + k) * (16 * 8);
#pragma unroll
                    for (int o2 = 0; o2 < 16; ++o2) {
                        unsigned long long wv = lds_u64(base + o2 * 8);
                        FFMA2(acc[o2], g2, wv);
                    }
                }
            }

            const size_t orow = ((size_t)i * N_NODES + j) * OUT;
#pragma unroll
            for (int o4 = 0; o4 < 8; ++o4) {
                float a, b, c, d;
                unpack2(acc[2 * o4 + 0], a, b);
                unpack2(acc[2 * o4 + 1], c, d);
                float4 v;
                v.x = swish_fast(a + b2f[4 * o4 + 0]);
                v.y = swish_fast(b + b2f[4 * o4 + 1]);
                v.z = swish_fast(c + b2f[4 * o4 + 2]);
                v.w = swish_fast(d + b2f[4 * o4 + 3]);
                *(float4*)(out + orow + 4 * o4) = v;
            }
        }
    }
#endif
}

// ---------------------------------------------------------------------------
// Harness entry. Inputs: Edges, Coordinates, Embeddings, W1, b1, W2, b2.
// Output: float32 (N, N, OUT).
// ---------------------------------------------------------------------------
extern "C" void kernel_launch(void* const* d_in, const int* in_sizes, int n_in,
                              void* d_out, int out_size) {
    const float* Edges  = (const float*)d_in[0];
    const float* Coords = (const float*)d_in[1];
    const float* Emb    = (const float*)d_in[2];
    const float* W1     = (const float*)d_in[3];
    const float* b1     = (const float*)d_in[4];
    const float* W2     = (const float*)d_in[5];
    const float* b2     = (const float*)d_in[6];
    float* out = (float*)d_out;

    precompute_AB<<<N_NODES / 4, 256>>>(Emb, W1);

    dim3 grid(N_NODES / (J_TILE * JITERS), N_NODES / I_TILE);  // (4, 128) = 512
    edge_mlp_tc<<<grid, THREADS, SM_TOTAL>>>(Edges, Coords, b1, W2, b2, out);
}

// round 13
// speedup vs baseline: 1.1024x; 1.1024x over previous
#include <cuda_runtime.h>
#include <cuda_bf16.h>
#include <cuda_fp16.h>
#include <cstdint>
#include <cstddef>

#define N_NODES 1024
#define F_IN    32
#define HID     64
#define OUT     32
#define I_TILE  8
#define J_TILE  16
#define JITERS  8     // j-tiles per block = 4 pairs
#define NPAIRS  (JITERS / 2)
#define THREADS 256

#if defined(__CUDA_ARCH__) && (defined(__CUDA_ARCH_FEAT_SM103_ALL) || \
                               defined(__CUDA_ARCH_FEAT_SM100_ALL) || \
                               defined(__CUDA_ARCH_FAMILY_SPECIFIC__))
#define USE_TC 1
#else
#define USE_TC 0
#endif

__device__ float g_A[N_NODES * HID];   // A[i,h] = Emb[i,:] . W1[h, :F]
__device__ float g_B[N_NODES * HID];   // B[j,h] = Emb[j,:] . W1[h, F:]

// ---------------------------------------------------------------------------
// Kernel 1: A/B precompute — smem-staged W1 (padded, conflict-free).
// ---------------------------------------------------------------------------
__global__ __launch_bounds__(256)
void precompute_AB(const float* __restrict__ Emb,
                   const float* __restrict__ W1) {
    __shared__ float w1s[HID][2 * F_IN + 1];
    __shared__ float embs[4][F_IN + 1];
    const int tid = threadIdx.x;
    const int ibase = blockIdx.x * 4;

    for (int p = tid; p < HID * 2 * F_IN; p += 256) {
        int r = p >> 6, c = p & 63;
        w1s[r][c] = W1[p];
    }
    if (tid < 4 * F_IN)
        embs[tid >> 5][tid & 31] = Emb[ibase * F_IN + tid];
    __syncthreads();

    const int il = tid >> 6;
    const int h  = tid & 63;
    float sa = 0.f, sb = 0.f;
#pragma unroll
    for (int f = 0; f < F_IN; ++f) {
        float e = embs[il][f];
        sa = fmaf(e, w1s[h][f], sa);
        sb = fmaf(e, w1s[h][F_IN + f], sb);
    }
    const int idx = (ibase + il) * HID + h;
    g_A[idx] = sa;
    g_B[idx] = sb;
}

// ---------------------------------------------------------------------------
// Helpers
// ---------------------------------------------------------------------------
__device__ __forceinline__ unsigned smem_u32(const void* p) {
    unsigned a;
    asm("{ .reg .u64 t; cvta.to.shared.u64 t, %1; cvt.u32.u64 %0, t; }"
        : "=r"(a) : "l"(p));
    return a;
}

__device__ __forceinline__ unsigned long long pack2(float lo, float hi) {
    unsigned long long r;
    asm("mov.b64 %0, {%1, %2};"
        : "=l"(r) : "r"(__float_as_uint(lo)), "r"(__float_as_uint(hi)));
    return r;
}

__device__ __forceinline__ void unpack2(unsigned long long v, float& lo, float& hi) {
    unsigned a, b;
    asm("mov.b64 {%0, %1}, %2;" : "=r"(a), "=r"(b) : "l"(v));
    lo = __uint_as_float(a);
    hi = __uint_as_float(b);
}

__device__ __forceinline__ unsigned long long lds_u64(unsigned addr) {
    unsigned long long r;
    asm volatile("ld.shared.b64 %0, [%1];" : "=l"(r) : "r"(addr));
    return r;
}

#define FFMA2(acc, a, b) \
    asm("fma.rn.f32x2 %0, %1, %2, %0;" : "+l"(acc) : "l"(a), "l"(b))

__device__ __forceinline__ float tanh_f(float x) {
    float t;
    asm("tanh.approx.f32 %0, %1;" : "=f"(t) : "f"(x));
    return t;
}

__device__ __forceinline__ float swish_fast(float x) {
    float h = 0.5f * x;
    float t = tanh_f(h);
    return fmaf(h, t, h);
}

// Given h = x/2 already: swish(x) = h*(1+tanh(h))
__device__ __forceinline__ float swish_from_half(float h) {
    float t = tanh_f(h);
    return fmaf(h, t, h);
}

__device__ __forceinline__ unsigned cvt2f16(float lo, float hi) {
    unsigned r;
    asm("cvt.rn.f16x2.f32 %0, %1, %2;" : "=r"(r) : "f"(hi), "f"(lo));
    return r;
}

#if USE_TC
__device__ __forceinline__ bool elect_one() {
    unsigned pred;
    asm volatile("{\n\t.reg .pred p;\n\telect.sync _|p, 0xFFFFFFFF;\n\t"
                 "selp.b32 %0, 1, 0, p;\n\t}" : "=r"(pred));
    return pred != 0;
}

__device__ __forceinline__ void mbar_init(unsigned addr, unsigned cnt) {
    asm volatile("mbarrier.init.shared.b64 [%0], %1;" :: "r"(addr), "r"(cnt) : "memory");
}

__device__ __forceinline__ void mbar_inval(unsigned addr) {
    asm volatile("mbarrier.inval.shared.b64 [%0];" :: "r"(addr) : "memory");
}

__device__ __forceinline__ void mbar_arrive(unsigned addr) {
    asm volatile("mbarrier.arrive.release.cta.shared::cta.b64 _, [%0];"
                 :: "r"(addr) : "memory");
}

__device__ __forceinline__ void mbar_wait(unsigned addr, unsigned parity) {
    asm volatile(
        "{\n\t.reg .pred P;\n\t"
        "WL_%=:\n\t"
        "mbarrier.try_wait.parity.acquire.cta.shared::cta.b64 P, [%0], %1, 0x989680;\n\t"
        "@P bra.uni WD_%=;\n\t"
        "bra.uni WL_%=;\n\t"
        "WD_%=:\n\t}"
        :: "r"(addr), "r"(parity) : "memory");
}

// SW128 K-major smem descriptor: layout=2, version=1, SBO=64, LBO=1
__device__ __forceinline__ unsigned long long sdesc(unsigned addr) {
    const unsigned long long base =
        (2ull << 61) | (1ull << 46) | (64ull << 32) | (1ull << 16);
    return base | ((unsigned long long)(addr >> 4) & 0x3FFF);
}

// idesc kind::f16: dtype=F32, atype=btype=F16(0), N=32, M=128 -> 0x8080010
#define MMA_IDESC ((1u << 4) | ((OUT / 8) << 17) | (8u << 24))

// TS-form: A operand in TMEM
__device__ __forceinline__ void mma_f16_ts(unsigned d_tmem, unsigned a_tmem,
                                           unsigned long long b_desc,
                                           unsigned en) {
    asm volatile(
        "{\n\t.reg .pred p;\n\t"
        "setp.ne.u32 p, %5, 0;\n\t"
        "tcgen05.mma.cta_group::1.kind::f16 [%0], [%1], %2, %3, {%4, %4, %4, %4}, p;\n\t"
        "}"
        :: "r"(d_tmem), "r"(a_tmem), "l"(b_desc), "r"(MMA_IDESC), "r"(0u), "r"(en)
        : "memory");
}

#define STTM_X16(addr, r) \
    asm volatile( \
        "tcgen05.st.sync.aligned.32x32b.x16.b32 [%0], " \
        "{%1, %2, %3, %4, %5, %6, %7, %8, " \
        " %9, %10, %11, %12, %13, %14, %15, %16};" \
        :: "r"(addr), \
           "r"((r)[0]),  "r"((r)[1]),  "r"((r)[2]),  "r"((r)[3]), \
           "r"((r)[4]),  "r"((r)[5]),  "r"((r)[6]),  "r"((r)[7]), \
           "r"((r)[8]),  "r"((r)[9]),  "r"((r)[10]), "r"((r)[11]), \
           "r"((r)[12]), "r"((r)[13]), "r"((r)[14]), "r"((r)[15]) \
        : "memory")

#define LDTM_X32(r, addr) \
    asm volatile( \
        "tcgen05.ld.sync.aligned.32x32b.x32.b32 " \
        "{%0, %1, %2, %3, %4, %5, %6, %7, " \
        " %8, %9, %10, %11, %12, %13, %14, %15, " \
        " %16, %17, %18, %19, %20, %21, %22, %23, " \
        " %24, %25, %26, %27, %28, %29, %30, %31}, [%32];" \
        : "=r"((r)[0]),  "=r"((r)[1]),  "=r"((r)[2]),  "=r"((r)[3]), \
          "=r"((r)[4]),  "=r"((r)[5]),  "=r"((r)[6]),  "=r"((r)[7]), \
          "=r"((r)[8]),  "=r"((r)[9]),  "=r"((r)[10]), "=r"((r)[11]), \
          "=r"((r)[12]), "=r"((r)[13]), "=r"((r)[14]), "=r"((r)[15]), \
          "=r"((r)[16]), "=r"((r)[17]), "=r"((r)[18]), "=r"((r)[19]), \
          "=r"((r)[20]), "=r"((r)[21]), "=r"((r)[22]), "=r"((r)[23]), \
          "=r"((r)[24]), "=r"((r)[25]), "=r"((r)[26]), "=r"((r)[27]), \
          "=r"((r)[28]), "=r"((r)[29]), "=r"((r)[30]), "=r"((r)[31]) \
        : "r"(addr))
#endif  // USE_TC

// ---------------------------------------------------------------------------
// Dynamic SMEM layout. Total 29568 B.
// ---------------------------------------------------------------------------
#define SM_TMEM   0
#define SM_FULL   8
#define SM_EMPTY  16
#define SM_BSF0   24
#define SM_BSF1   32
#define SM_BSE0   40
#define SM_BSE1   48
#define SM_WHI    1024                    // 32 x 64 f16 SW128 = 4KB
#define SM_WLO    (SM_WHI + 4096)         // 5120
#define SM_BS0    (SM_WLO + 4096)         // 9216: 4 tile bufs x 4KB (buf=slot*2+tt)
#define SM_AS     (SM_BS0 + 16384)        // 25600 (8 rows x 64 f = 2KB)
#define SM_B1     (SM_AS + 2048)          // 27648 (0.5*b1)
#define SM_B2     (SM_B1 + 256)           // 27904 (0.5*b2)
#define SM_CJ     (SM_B2 + 128)           // 28032 (128 j x 3 f = 1536B)
#define SM_TOTAL  (SM_CJ + 1536)          // 29568

// Fallback layout (front of same buffer)
#define FB_W2P  0
#define FB_B1   (FB_W2P + HID * 16 * 8)
#define FB_B2   (FB_B1 + HID * 4)

#define SWZ(off) ((off) ^ (((off) >> 3) & 0x70))
// Bs addressing: tile buffer buf (0..3), row jl, float4 slot c4 at (c4^jl)*16
#define BS_ADDR(buf, jl, c4) \
    (SM_BS0 + ((unsigned)(buf) << 12) + ((jl) << 8) + ((unsigned)((c4) ^ (jl)) << 4))

// TMEM column offsets (alloc 128 cols): pair of D tiles + pair of A tiles
#define TM_DA 0
#define TM_DB 32
#define TM_AA 64
#define TM_AB 96

// ---------------------------------------------------------------------------
// Kernel 2: warp-specialized fused edge MLP, PAIR of j-tiles per handshake.
// warps 0-3 producers: h1 for 2 edges/thread (shared A/b1 loads), STTM x4,
//                      16 MMA dispatches, ONE commit per 256 edges.
// warps 4-7 consumers: 2x LDTM x32, 2 epilogues, B pair staging ahead.
// ---------------------------------------------------------------------------
__global__ __launch_bounds__(THREADS, 3)
void edge_mlp_tc(const float* __restrict__ Edges,
                 const float* __restrict__ Coords,
                 const float* __restrict__ b1,
                 const float* __restrict__ W2,
                 const float* __restrict__ b2,
                 float* __restrict__ out) {
    extern __shared__ char smem[];
    const int tid  = threadIdx.x;
    const int warp = tid >> 5;
    const int ibase = blockIdx.y * I_TILE;
    const int jblk  = blockIdx.x * (J_TILE * JITERS);

#if USE_TC
    const unsigned sb = smem_u32(smem);
    if (warp == 0) {
        asm volatile("tcgen05.alloc.cta_group::1.sync.aligned.shared::cta.b32 [%0], %1;"
                     :: "r"(sb + SM_TMEM), "r"(128u) : "memory");
        asm volatile("tcgen05.relinquish_alloc_permit.cta_group::1.sync.aligned;");
    }
    if (tid == 0) {
        mbar_init(sb + SM_FULL, 1);     // commit (1 per pair)
        mbar_init(sb + SM_EMPTY, 4);    // 4 consumer warps
        mbar_init(sb + SM_BSF0, 4);     // pair-slot staged (consumer warps)
        mbar_init(sb + SM_BSF1, 4);
        mbar_init(sb + SM_BSE0, 4);     // pair-slot consumed (producer warps)
        mbar_init(sb + SM_BSE1, 4);
    }

    // ---- one-time staging: W2 (fp16 hi/lo, SW128), A rows, 0.5*b1/b2, Cj ----
    for (int p = tid; p < OUT * 32; p += THREADS) {
        int o = p >> 5, h2 = p & 31;
        float w0 = W2[o * HID + 2 * h2];
        float w1 = W2[o * HID + 2 * h2 + 1];
        unsigned hi = cvt2f16(w0, w1);
        float r0 = w0 - __half2float(__ushort_as_half((unsigned short)(hi & 0xFFFF)));
        float r1 = w1 - __half2float(__ushort_as_half((unsigned short)(hi >> 16)));
        unsigned lo = cvt2f16(r0, r1);
        unsigned sw = SWZ((unsigned)(o * 128 + h2 * 4));
        *(unsigned*)(smem + SM_WHI + sw) = hi;
        *(unsigned*)(smem + SM_WLO + sw) = lo;
    }
    if (tid < 128)
        ((float4*)(smem + SM_AS))[tid] = ((const float4*)(g_A + ibase * HID))[tid];
    if (tid < HID) ((float*)(smem + SM_B1))[tid] = 0.5f * b1[tid];
    else if (tid < HID + OUT) ((float*)(smem + SM_B2))[tid - HID] = 0.5f * b2[tid - HID];
    for (int p = tid; p < 3 * J_TILE * JITERS; p += THREADS)
        ((float*)(smem + SM_CJ))[p] = Coords[jblk * 3 + p];

    asm volatile("fence.proxy.async.shared::cta;" ::: "memory");
    __syncthreads();

    unsigned tmem;
    asm("ld.shared.b32 %0, [%1];" : "=r"(tmem) : "r"(sb + SM_TMEM));

    if (tid < 128) {
        // =========================== PRODUCERS ===========================
        const int irow = tid >> 4;
        const int i    = ibase + irow;
        const int jl   = tid & 15;
        const unsigned warp_off = (unsigned)warp << 21;

        const float cx = Coords[i * 3 + 0];
        const float cy = Coords[i * 3 + 1];
        const float cz = Coords[i * 3 + 2];

        const float4* Asr = (const float4*)(smem + SM_AS + irow * 256);
        const float4* b1s = (const float4*)(smem + SM_B1);   // pre-halved
        const float*  CjS = (const float*)(smem + SM_CJ);
        const unsigned long long whiD = sdesc(sb + SM_WHI);
        const unsigned long long wloD = sdesc(sb + SM_WLO);

        const float* erow = Edges + (size_t)i * N_NODES + jblk + jl;
        float eA = __ldg(erow);
        float eB = __ldg(erow + J_TILE);

        for (int t = 0; t < NPAIRS; ++t) {
            const int slot = t & 1;
            const int bufA = slot * 2, bufB = slot * 2 + 1;

            float ecA = eA, ecB = eB;
            if (t < NPAIRS - 1) {
                eA = __ldg(erow + (2 * t + 2) * J_TILE);
                eB = __ldg(erow + (2 * t + 3) * J_TILE);
            }

            int cjx = (2 * t * J_TILE + jl) * 3;
            float dx = cx - CjS[cjx + 0];
            float dy = cy - CjS[cjx + 1];
            float dz = cz - CjS[cjx + 2];
            float d2 = dx * dx + dy * dy + dz * dz;
            float whA = (d2 > 0.f) ? 0.5f * ecA * (d2 * rsqrtf(d2)) : 0.f;
            cjx += 3 * J_TILE;
            dx = cx - CjS[cjx + 0];
            dy = cy - CjS[cjx + 1];
            dz = cz - CjS[cjx + 2];
            d2 = dx * dx + dy * dy + dz * dz;
            float whB = (d2 > 0.f) ? 0.5f * ecB * (d2 * rsqrtf(d2)) : 0.f;

            // wait for consumer-staged pair slot (normally already complete)
            mbar_wait(sb + SM_BSF0 + slot * 8, (t >> 1) & 1);

            unsigned vA[16], vB[16];
            // ---- half 1: hidden units 0..31, both edges (shared A/b1) ----
#pragma unroll
            for (int c = 0; c < 4; ++c) {
                float4 a0 = Asr[2 * c];
                float4 a1 = Asr[2 * c + 1];
                float4 q0 = b1s[2 * c];
                float4 q1 = b1s[2 * c + 1];
                float4 pA0 = *(const float4*)(smem + BS_ADDR(bufA, jl, 2 * c));
                float4 pA1 = *(const float4*)(smem + BS_ADDR(bufA, jl, 2 * c + 1));
                float4 pB0 = *(const float4*)(smem + BS_ADDR(bufB, jl, 2 * c));
                float4 pB1 = *(const float4*)(smem + BS_ADDR(bufB, jl, 2 * c + 1));

                float g0 = swish_from_half(fmaf(whA, a0.x + pA0.x, q0.x));
                float g1 = swish_from_half(fmaf(whA, a0.y + pA0.y, q0.y));
                float g2 = swish_from_half(fmaf(whA, a0.z + pA0.z, q0.z));
                float g3 = swish_from_half(fmaf(whA, a0.w + pA0.w, q0.w));
                float g4 = swish_from_half(fmaf(whA, a1.x + pA1.x, q1.x));
                float g5 = swish_from_half(fmaf(whA, a1.y + pA1.y, q1.y));
                float g6 = swish_from_half(fmaf(whA, a1.z + pA1.z, q1.z));
                float g7 = swish_from_half(fmaf(whA, a1.w + pA1.w, q1.w));
                vA[4 * c + 0] = cvt2f16(g0, g1);
                vA[4 * c + 1] = cvt2f16(g2, g3);
                vA[4 * c + 2] = cvt2f16(g4, g5);
                vA[4 * c + 3] = cvt2f16(g6, g7);

                g0 = swish_from_half(fmaf(whB, a0.x + pB0.x, q0.x));
                g1 = swish_from_half(fmaf(whB, a0.y + pB0.y, q0.y));
                g2 = swish_from_half(fmaf(whB, a0.z + pB0.z, q0.z));
                g3 = swish_from_half(fmaf(whB, a0.w + pB0.w, q0.w));
                g4 = swish_from_half(fmaf(whB, a1.x + pB1.x, q1.x));
                g5 = swish_from_half(fmaf(whB, a1.y + pB1.y, q1.y));
                g6 = swish_from_half(fmaf(whB, a1.z + pB1.z, q1.z));
                g7 = swish_from_half(fmaf(whB, a1.w + pB1.w, q1.w));
                vB[4 * c + 0] = cvt2f16(g0, g1);
                vB[4 * c + 1] = cvt2f16(g2, g3);
                vB[4 * c + 2] = cvt2f16(g4, g5);
                vB[4 * c + 3] = cvt2f16(g6, g7);
            }

            // A reuse safe only after MMA of pair t-1 completed
            if (t >= 1) mbar_wait(sb + SM_FULL, (t - 1) & 1);
            STTM_X16(tmem + TM_AA + warp_off, vA);
            STTM_X16(tmem + TM_AB + warp_off, vB);

            // ---- half 2: hidden units 32..63 ----
#pragma unroll
            for (int c = 4; c < 8; ++c) {
                float4 a0 = Asr[2 * c];
                float4 a1 = Asr[2 * c + 1];
                float4 q0 = b1s[2 * c];
                float4 q1 = b1s[2 * c + 1];
                float4 pA0 = *(const float4*)(smem + BS_ADDR(bufA, jl, 2 * c));
                float4 pA1 = *(const float4*)(smem + BS_ADDR(bufA, jl, 2 * c + 1));
                float4 pB0 = *(const float4*)(smem + BS_ADDR(bufB, jl, 2 * c));
                float4 pB1 = *(const float4*)(smem + BS_ADDR(bufB, jl, 2 * c + 1));

                float g0 = swish_from_half(fmaf(whA, a0.x + pA0.x, q0.x));
                float g1 = swish_from_half(fmaf(whA, a0.y + pA0.y, q0.y));
                float g2 = swish_from_half(fmaf(whA, a0.z + pA0.z, q0.z));
                float g3 = swish_from_half(fmaf(whA, a0.w + pA0.w, q0.w));
                float g4 = swish_from_half(fmaf(whA, a1.x + pA1.x, q1.x));
                float g5 = swish_from_half(fmaf(whA, a1.y + pA1.y, q1.y));
                float g6 = swish_from_half(fmaf(whA, a1.z + pA1.z, q1.z));
                float g7 = swish_from_half(fmaf(whA, a1.w + pA1.w, q1.w));
                vA[4 * (c - 4) + 0] = cvt2f16(g0, g1);
                vA[4 * (c - 4) + 1] = cvt2f16(g2, g3);
                vA[4 * (c - 4) + 2] = cvt2f16(g4, g5);
                vA[4 * (c - 4) + 3] = cvt2f16(g6, g7);

                g0 = swish_from_half(fmaf(whB, a0.x + pB0.x, q0.x));
                g1 = swish_from_half(fmaf(whB, a0.y + pB0.y, q0.y));
                g2 = swish_from_half(fmaf(whB, a0.z + pB0.z, q0.z));
                g3 = swish_from_half(fmaf(whB, a0.w + pB0.w, q0.w));
                g4 = swish_from_half(fmaf(whB, a1.x + pB1.x, q1.x));
                g5 = swish_from_half(fmaf(whB, a1.y + pB1.y, q1.y));
                g6 = swish_from_half(fmaf(whB, a1.z + pB1.z, q1.z));
                g7 = swish_from_half(fmaf(whB, a1.w + pB1.w, q1.w));
                vB[4 * (c - 4) + 0] = cvt2f16(g0, g1);
                vB[4 * (c - 4) + 1] = cvt2f16(g2, g3);
                vB[4 * (c - 4) + 2] = cvt2f16(g4, g5);
                vB[4 * (c - 4) + 3] = cvt2f16(g6, g7);
            }

            // Bs pair fully consumed -> release for restaging
            __syncwarp();
            if ((tid & 31) == 0) mbar_arrive(sb + SM_BSE0 + slot * 8);

            STTM_X16(tmem + TM_AA + 16 + warp_off, vA);
            STTM_X16(tmem + TM_AB + 16 + warp_off, vB);
            asm volatile("tcgen05.wait::st.sync.aligned;" ::: "memory");
            asm volatile("tcgen05.fence::before_thread_sync;" ::: "memory");

            asm volatile("bar.sync 1, 128;" ::: "memory");   // all STTM done

            if (warp == 0 && elect_one()) {
                asm volatile("tcgen05.fence::after_thread_sync;" ::: "memory");
                // D reuse safe only after consumer drained pair t-1
                if (t >= 1) mbar_wait(sb + SM_EMPTY, (t - 1) & 1);
                unsigned en = 0;
#pragma unroll
                for (int k = 0; k < 4; ++k) { mma_f16_ts(tmem + TM_DA, tmem + TM_AA + k * 8, whiD + 2 * k, en); en = 1; }
#pragma unroll
                for (int k = 0; k < 4; ++k) { mma_f16_ts(tmem + TM_DA, tmem + TM_AA + k * 8, wloD + 2 * k, 1); }
                en = 0;
#pragma unroll
                for (int k = 0; k < 4; ++k) { mma_f16_ts(tmem + TM_DB, tmem + TM_AB + k * 8, whiD + 2 * k, en); en = 1; }
#pragma unroll
                for (int k = 0; k < 4; ++k) { mma_f16_ts(tmem + TM_DB, tmem + TM_AB + k * 8, wloD + 2 * k, 1); }
                asm volatile(
                    "tcgen05.commit.cta_group::1.mbarrier::arrive::one.shared::cluster.b64 [%0];"
                    :: "r"(sb + SM_FULL) : "memory");
            }
        }
    } else {
        // =========================== CONSUMERS ===========================
        const int ctid = tid - 128;
        const int i    = ibase + (ctid >> 4);
        const int jfix = ctid & 15;
        const float4* b2s = (const float4*)(smem + SM_B2);   // pre-halved

        // prologue: stage pairs 0 and 1 (4 tiles)
#pragma unroll
        for (int u = 0; u < 2; ++u) {
#pragma unroll
            for (int tt = 0; tt < 2; ++tt) {
                const float4* src =
                    (const float4*)(g_B + (jblk + (2 * u + tt) * J_TILE) * HID);
#pragma unroll
                for (int p = ctid; p < 256; p += 128) {
                    int jj = p >> 4, c4 = p & 15;
                    *(float4*)(smem + BS_ADDR(u * 2 + tt, jj, c4)) = src[p];
                }
            }
            __syncwarp();
            if ((tid & 31) == 0) mbar_arrive(sb + SM_BSF0 + u * 8);
        }

        for (int t = 0; t < NPAIRS; ++t) {
            const int slot = t & 1;
            mbar_wait(sb + SM_FULL, t & 1);
            asm volatile("tcgen05.fence::after_thread_sync;" ::: "memory");

            const size_t orowA =
                ((size_t)i * N_NODES + (jblk + 2 * t * J_TILE + jfix)) * OUT;

            unsigned d[32];
            // ---- edge A ----
            LDTM_X32(d, tmem + TM_DA);
            asm volatile("tcgen05.wait::ld.sync.aligned;" ::: "memory");
#pragma unroll
            for (int q = 0; q < 8; ++q) {
                float4 bq = b2s[q];                       // 0.5*b2
                float h0 = fmaf(__uint_as_float(d[4 * q + 0]), 0.5f, bq.x);
                float h1 = fmaf(__uint_as_float(d[4 * q + 1]), 0.5f, bq.y);
                float h2 = fmaf(__uint_as_float(d[4 * q + 2]), 0.5f, bq.z);
                float h3 = fmaf(__uint_as_float(d[4 * q + 3]), 0.5f, bq.w);
                float4 o4;
                o4.x = swish_from_half(h0);
                o4.y = swish_from_half(h1);
                o4.z = swish_from_half(h2);
                o4.w = swish_from_half(h3);
                *(float4*)(out + orowA + 4 * q) = o4;
            }
            // ---- edge B ----
            LDTM_X32(d, tmem + TM_DB);
            asm volatile("tcgen05.wait::ld.sync.aligned;" ::: "memory");
            asm volatile("tcgen05.fence::before_thread_sync;" ::: "memory");
            if ((tid & 31) == 0) mbar_arrive(sb + SM_EMPTY);   // D drained
            const size_t orowB = orowA + (size_t)J_TILE * OUT;
#pragma unroll
            for (int q = 0; q < 8; ++q) {
                float4 bq = b2s[q];
                float h0 = fmaf(__uint_as_float(d[4 * q + 0]), 0.5f, bq.x);
                float h1 = fmaf(__uint_as_float(d[4 * q + 1]), 0.5f, bq.y);
                float h2 = fmaf(__uint_as_float(d[4 * q + 2]), 0.5f, bq.z);
                float h3 = fmaf(__uint_as_float(d[4 * q + 3]), 0.5f, bq.w);
                float4 o4;
                o4.x = swish_from_half(h0);
                o4.y = swish_from_half(h1);
                o4.z = swish_from_half(h2);
                o4.w = swish_from_half(h3);
                *(float4*)(out + orowB + 4 * q) = o4;
            }

            // restage pair slot with pair t+2
            if (t < NPAIRS - 2) {
                mbar_wait(sb + SM_BSE0 + slot * 8, (t >> 1) & 1);
#pragma unroll
                for (int tt = 0; tt < 2; ++tt) {
                    const float4* src =
                        (const float4*)(g_B + (jblk + (2 * (t + 2) + tt) * J_TILE) * HID);
#pragma unroll
                    for (int p = ctid; p < 256; p += 128) {
                        int jj = p >> 4, c4 = p & 15;
                        *(float4*)(smem + BS_ADDR(slot * 2 + tt, jj, c4)) = src[p];
                    }
                }
                __syncwarp();
                if ((tid & 31) == 0) mbar_arrive(sb + SM_BSF0 + slot * 8);
            }
        }
    }

    __syncthreads();
    if (tid == 0) {
        mbar_inval(sb + SM_FULL);
        mbar_inval(sb + SM_EMPTY);
        mbar_inval(sb + SM_BSF0);
        mbar_inval(sb + SM_BSF1);
        mbar_inval(sb + SM_BSE0);
        mbar_inval(sb + SM_BSE1);
    }
    __syncthreads();
    if (warp == 0) {
        asm volatile("tcgen05.dealloc.cta_group::1.sync.aligned.b32 %0, %1;"
                     :: "r"(tmem), "r"(128u));
    }
#else
    // ===================== scalar FFMA2 fallback (compile-only) =====================
    float2* W2p = (float2*)(smem + FB_W2P);
    float*  b1f = (float*)(smem + FB_B1);
    float*  b2f = (float*)(smem + FB_B2);
    for (int p = tid; p < HID * 16; p += THREADS) {
        int h = p >> 4, o2 = p & 15;
        W2p[h * 16 + o2] = make_float2(W2[(2 * o2) * HID + h],
                                       W2[(2 * o2 + 1) * HID + h]);
    }
    if (tid < HID) b1f[tid] = b1[tid];
    if (tid < OUT) b2f[tid] = b2[tid];
    __syncthreads();

    if (tid < 128) {
        const int i  = ibase + (tid >> 4);
        const int jl = tid & 15;
        const float cx = Coords[i * 3 + 0];
        const float cy = Coords[i * 3 + 1];
        const float cz = Coords[i * 3 + 2];
        const float4* Ar = (const float4*)(g_A + i * HID);
        const unsigned w2sm = smem_u32(W2p);

        for (int it = 0; it < JITERS; ++it) {
            const int j = jblk + it * J_TILE + jl;
            float dx = cx - Coords[j * 3 + 0];
            float dy = cy - Coords[j * 3 + 1];
            float dz = cz - Coords[j * 3 + 2];
            float d2 = dx * dx + dy * dy + dz * dz;
            float dist = (d2 > 0.f) ? d2 * rsqrtf(d2) : 0.f;
            const float w = Edges[(size_t)i * N_NODES + j] * dist;

            const float4* Br = (const float4*)(g_B + j * HID);
            unsigned long long acc[16];
#pragma unroll
            for (int o2 = 0; o2 < 16; ++o2) acc[o2] = 0ull;

#pragma unroll 4
            for (int c = 0; c < 16; ++c) {
                float4 a  = __ldg(Ar + c);
                float4 bb = __ldg(Br + c);
                float4 bv = __ldg(((const float4*)b1) + c);
                float av[4] = {a.x, a.y, a.z, a.w};
                float pv[4] = {bb.x, bb.y, bb.z, bb.w};
                float cv[4] = {bv.x, bv.y, bv.z, bv.w};
#pragma unroll
                for (int k = 0; k < 4; ++k) {
                    float g = swish_fast(fmaf(w, av[k] + pv[k], cv[k]));
                    unsigned long long g2 = pack2(g, g);
                    unsigned base = w2sm + (unsigned)(4 * c + k) * (16 * 8);
#pragma unroll
                    for (int o2 = 0; o2 < 16; ++o2) {
                        unsigned long long wv = lds_u64(base + o2 * 8);
                        FFMA2(acc[o2], g2, wv);
                    }
                }
            }

            const size_t orow = ((size_t)i * N_NODES + j) * OUT;
#pragma unroll
            for (int o4 = 0; o4 < 8; ++o4) {
                float a, b, c, d;
                unpack2(acc[2 * o4 + 0], a, b);
                unpack2(acc[2 * o4 + 1], c, d);
                float4 v;
                v.x = swish_fast(a + b2f[4 * o4 + 0]);
                v.y = swish_fast(b + b2f[4 * o4 + 1]);
                v.z = swish_fast(c + b2f[4 * o4 + 2]);
                v.w = swish_fast(d + b2f[4 * o4 + 3]);
                *(float4*)(out + orow + 4 * o4) = v;
            }
        }
    }
#endif
}

// ---------------------------------------------------------------------------
// Harness entry. Inputs: Edges, Coordinates, Embeddings, W1, b1, W2, b2.
// Output: float32 (N, N, OUT).
// ---------------------------------------------------------------------------
extern "C" void kernel_launch(void* const* d_in, const int* in_sizes, int n_in,
                              void* d_out, int out_size) {
    const float* Edges  = (const float*)d_in[0];
    const float* Coords = (const float*)d_in[1];
    const float* Emb    = (const float*)d_in[2];
    const float* W1     = (const float*)d_in[3];
    const float* b1     = (const float*)d_in[4];
    const float* W2     = (const float*)d_in[5];
    const float* b2     = (const float*)d_in[6];
    float* out = (float*)d_out;

    precompute_AB<<<N_NODES / 4, 256>>>(Emb, W1);

    dim3 grid(N_NODES / (J_TILE * JITERS), N_NODES / I_TILE);  // (8, 128) = 1024
    edge_mlp_tc<<<grid, THREADS, SM_TOTAL>>>(Edges, Coords, b1, W2, b2, out);
}